// round 16
// baseline (speedup 1.0000x reference)
#include <cuda_runtime.h>
#include <cuda_fp16.h>
#include <cstdint>

// ---------------------------------------------------------------------------
// CompositionModel — fp16 mma.sync m16n8k16 (f16 acc) + ldmatrix, 64x64 warp
// tiles (TILE_M=128), cp.async weight staging, 2 CTAs/SM, last-CTA finalize.
//   Xp = [fp16(log1p X) | fp16(Z[c2b])]  (N x 160)
//   h1 = relu(Xp@W1+b1); h2 = relu(h1@W2+b2); Xc = h2@W3+b3; Y = segmean(Xc)
// R15 profile: L1=53.7% vs tensor=45.4% — smem port (128B/cyc/SM) can't feed
// HMMA at 1.5 wf/MMA. 64x64 warp tile -> 1.0 wf/MMA; barriers and cp.async
// traffic per cell halve. acc[4][8][2] f16 = 64 regs keeps us under 128.
// ---------------------------------------------------------------------------

#define N_CELLS 500000
#define D_X     128
#define D_Z     32
#define D_IN    160
#define HID     256
#define D_OUT   16
#define BATCH   512
#define TILE_M  128
#define NTILES  ((N_CELLS + TILE_M - 1) / TILE_M)   // 3907

#define LDAW    132      // act row stride in words; 528B rows -> LDSM conflict-free
#define LDBW    20       // weight-stage row stride (words); 80B rows -> LDSM conflict-free
#define LDW3    132      // W3 stage row stride (words)
#define KC      32       // fp16 k per chunk (2 k-steps of 16)

// smem byte offsets
#define SM_BUF  0                                  // 128 x LDAW words = 67584 B
#define SM_STG0 67584                              // 20480 B
#define SM_STG1 88064                              // 20480 B
#define SM_MISC 108544
// misc: seg[128](4B) cb[128](4B) b1h[128](u32) b2h[128](u32) b3[16](f32)
#define SMEM_BYTES (SM_MISC + 128*4 + 128*4 + 128*4 + 128*4 + 16*4)  // 110656; x2 = 221312 <= 233472

// __device__ scratch: weights transposed [N][K] fp16 (K contiguous)
__device__ __half gW1t[256 * D_IN];
__device__ __half gW2t[256 * HID];
__device__ __half gW3t[16 * HID];
__device__ float gSum[BATCH * D_OUT];
__device__ float gCnt[BATCH];
__device__ unsigned gDone;

__device__ __forceinline__ void cp16(void* dst_smem, const void* src) {
    uint32_t d = (uint32_t)__cvta_generic_to_shared(dst_smem);
    asm volatile("cp.async.cg.shared.global [%0], [%1], 16;\n" :: "r"(d), "l"(src));
}
#define CP_COMMIT() asm volatile("cp.async.commit_group;\n")
#define CP_WAIT(n)  asm volatile("cp.async.wait_group %0;\n" :: "n"(n))

// m16n8k16 fp16 inputs, FP16 accumulators (2 regs)
__device__ __forceinline__ void mma16h(uint32_t c[2],
                                       uint32_t a0, uint32_t a1, uint32_t a2, uint32_t a3,
                                       uint32_t b0, uint32_t b1) {
    asm volatile(
        "mma.sync.aligned.m16n8k16.row.col.f16.f16.f16.f16 "
        "{%0,%1}, {%2,%3,%4,%5}, {%6,%7}, {%0,%1};\n"
        : "+r"(c[0]), "+r"(c[1])
        : "r"(a0), "r"(a1), "r"(a2), "r"(a3), "r"(b0), "r"(b1));
}

// ldmatrix: 4x 8x8 b16 matrices, one 32-bit fragment word per thread per matrix
__device__ __forceinline__ void ldsm_x4(uint32_t (&r)[4], uint32_t addr) {
    asm volatile("ldmatrix.sync.aligned.m8n8.x4.shared.b16 {%0,%1,%2,%3}, [%4];"
                 : "=r"(r[0]), "=r"(r[1]), "=r"(r[2]), "=r"(r[3]) : "r"(addr));
}

__device__ __forceinline__ uint32_t h2bits(__half2 h) {
    return *reinterpret_cast<uint32_t*>(&h);
}
__device__ __forceinline__ __half2 bits2h(uint32_t u) {
    return *reinterpret_cast<__half2*>(&u);
}

// prefetch one KC-k-slice of a [256][pitch] fp16 weight matrix into a stage
__device__ __forceinline__ void prefetch_chunk(char* stg, const __half* Wt,
                                               int pitch, int chunk) {
    int t = threadIdx.x;
#pragma unroll
    for (int u = 0; u < 4; u++) {
        int idx = t + u * 256;            // 0..1023
        int n = idx >> 2, j = idx & 3;    // j: 16B piece (8 fp16) within KC
        cp16(stg + (n * LDBW + j * 4) * 4, Wt + (size_t)n * pitch + chunk * KC + j * 8);
    }
}
// prefetch W3 (16 x 256 fp16 = 8 KB) into a stage, row stride LDW3 words
__device__ __forceinline__ void prefetch_w3(char* stg) {
    int t = threadIdx.x;
#pragma unroll
    for (int u = 0; u < 2; u++) {
        int idx = t + u * 256;            // 0..511
        int n = idx >> 5, j = idx & 31;   // 32 pieces of 8 fp16 per row
        cp16(stg + (n * LDW3 + j * 4) * 4, gW3t + n * HID + j * 8);
    }
}

// one KC-slice of the 64x64 warp-tile GEMM via ldmatrix (2 k-steps of 16)
__device__ __forceinline__ void compute_chunk(uint32_t aLane, uint32_t bLane,
                                              int kbase, uint32_t (&acc)[4][8][2]) {
#pragma unroll
    for (int kk = 0; kk < KC; kk += 16) {
        uint32_t koffA = (uint32_t)(((kbase + kk) >> 1) * 4);
        uint32_t koffB = (uint32_t)((kk >> 1) * 4);
        uint32_t a[4][4];
#pragma unroll
        for (int mt = 0; mt < 4; mt++)
            ldsm_x4(a[mt], aLane + mt * (16 * LDAW * 4) + koffA);
        uint32_t b[4][4];
#pragma unroll
        for (int p = 0; p < 4; p++)
            ldsm_x4(b[p], bLane + p * (16 * LDBW * 4) + koffB);
#pragma unroll
        for (int p = 0; p < 4; p++)
#pragma unroll
            for (int j = 0; j < 2; j++)
#pragma unroll
                for (int mt = 0; mt < 4; mt++)
                    mma16h(acc[mt][2 * p + j],
                           a[mt][0], a[mt][1], a[mt][2], a[mt][3],
                           b[p][2 * j], b[p][2 * j + 1]);
    }
}

// f16 acc -> relu(+bias, packed) -> act buffer
__device__ __forceinline__ void store_act(uint32_t* sBuf, const uint32_t* bias2,
                                          int m0, int n0, int g, int tig,
                                          uint32_t (&acc)[4][8][2]) {
    const __half2 z2 = __float2half2_rn(0.f);
#pragma unroll
    for (int mt = 0; mt < 4; mt++) {
        int r0 = m0 + mt * 16 + g;
#pragma unroll
        for (int nt = 0; nt < 8; nt++) {
            int wc = (n0 >> 1) + nt * 4 + tig;
            __half2 bv = bits2h(bias2[wc]);
            sBuf[r0 * LDAW + wc]       = h2bits(__hmax2(__hadd2(bits2h(acc[mt][nt][0]), bv), z2));
            sBuf[(r0 + 8) * LDAW + wc] = h2bits(__hmax2(__hadd2(bits2h(acc[mt][nt][1]), bv), z2));
        }
    }
}

// ---------------------------------------------------------------------------
__global__ void prep_kernel(const float* __restrict__ W1, const float* __restrict__ W2,
                            const float* __restrict__ W3) {
    int stride = gridDim.x * blockDim.x;
    int t0 = blockIdx.x * blockDim.x + threadIdx.x;
    for (int i = t0; i < 256 * D_IN; i += stride) {
        int n = i / D_IN, k = i - n * D_IN;
        gW1t[i] = __float2half_rn(W1[k * 256 + n]);
    }
    for (int i = t0; i < 256 * HID; i += stride) {
        int n = i >> 8, k = i & 255;
        gW2t[i] = __float2half_rn(W2[k * 256 + n]);
    }
    for (int i = t0; i < 16 * HID; i += stride) {
        int n = i >> 8, k = i & 255;
        gW3t[i] = __float2half_rn(W3[k * 16 + n]);
    }
    for (int i = t0; i < BATCH * D_OUT; i += stride) gSum[i] = 0.f;
    for (int i = t0; i < BATCH; i += stride) gCnt[i] = 0.f;
    if (t0 == 0) gDone = 0u;
}

// ---------------------------------------------------------------------------
// 8 warps as 2(Mg of 64 rows) x 4(Ng of 64 cols); 2 CTAs resident per SM.
// Last CTA (atomic counter) computes Y = gSum/gCnt and writes d_out.
// ---------------------------------------------------------------------------
__global__ __launch_bounds__(256, 2) void fused_kernel(
    const float* __restrict__ X, const float* __restrict__ Z,
    const float* __restrict__ b1, const float* __restrict__ b2,
    const float* __restrict__ b3,
    const int* __restrict__ c2b, const int* __restrict__ sidx,
    float* __restrict__ out) {
    extern __shared__ char smem[];
    uint32_t* sBuf = (uint32_t*)(smem + SM_BUF);     // 128 x LDAW words (fp16 pairs)
    char*     stg0 = smem + SM_STG0;
    char*     stg1 = smem + SM_STG1;
    int*      sSeg = (int*)(smem + SM_MISC);
    int*      sCB  = sSeg + 128;
    uint32_t* sB1h = (uint32_t*)(sCB + 128);         // 128 half2 words
    uint32_t* sB2h = sB1h + 128;
    float*    sB3  = (float*)(sB2h + 128);           // 16 floats
    __shared__ unsigned sLast;

    const int tid  = threadIdx.x;
    const int lane = tid & 31;
    const int wid  = tid >> 5;
    const int g    = lane >> 2;
    const int tig  = lane & 3;
    const int base = blockIdx.x * TILE_M;

    // kick off W1 chunk 0 immediately (overlaps input staging)
    prefetch_chunk(stg0, gW1t, D_IN, 0);
    CP_COMMIT();

    // ---- indices + biases (biases packed to half2 words) ----
    if (tid < 128) {
        int c = base + tid, cb = 0, seg = -1;
        if (c < N_CELLS) { cb = c2b[c]; seg = sidx[cb]; }
        sCB[tid] = cb;
        sSeg[tid] = seg;
        sB1h[tid] = h2bits(__floats2half2_rn(b1[2 * tid], b1[2 * tid + 1]));
        sB2h[tid] = h2bits(__floats2half2_rn(b2[2 * tid], b2[2 * tid + 1]));
    }
    if (tid < 16) sB3[tid] = b3[tid];
    if (tid == 0) sLast = 0u;
    __syncthreads();

    // ---- build Xp tile (fp16): words 0..63 = log1p(X), 64..79 = Z gather ----
#pragma unroll
    for (int u = 0; u < 16; u++) {               // X: 4096 float4 pieces (128 rows x 32)
        int idx = tid + u * 256;
        int row = idx >> 5, p = idx & 31;
        int cell = base + row;
        uint2 w = make_uint2(0u, 0u);
        if (cell < N_CELLS) {
            float4 x = *reinterpret_cast<const float4*>(X + (size_t)cell * D_X + p * 4);
            w.x = h2bits(__floats2half2_rn(__logf(1.f + x.x), __logf(1.f + x.y)));
            w.y = h2bits(__floats2half2_rn(__logf(1.f + x.z), __logf(1.f + x.w)));
        }
        *reinterpret_cast<uint2*>(sBuf + row * LDAW + 2 * p) = w;
    }
#pragma unroll
    for (int u = 0; u < 4; u++) {                // Z: 1024 float4 pieces (128 rows x 8)
        int idx = tid + u * 256;
        int row = idx >> 3, p = idx & 7;
        int cell = base + row;
        uint2 w = make_uint2(0u, 0u);
        if (cell < N_CELLS) {
            float4 z = *reinterpret_cast<const float4*>(Z + (size_t)sCB[row] * D_Z + p * 4);
            w.x = h2bits(__floats2half2_rn(z.x, z.y));
            w.y = h2bits(__floats2half2_rn(z.z, z.w));
        }
        *reinterpret_cast<uint2*>(sBuf + row * LDAW + 64 + 2 * p) = w;
    }
    __syncthreads();

    const int mg = wid & 1, ng = wid >> 1;
    const int m0 = mg * 64, n0 = ng * 64;

    // per-lane ldmatrix base addresses (byte, shared space)
    const uint32_t uBuf  = (uint32_t)__cvta_generic_to_shared(sBuf);
    const uint32_t uStg0 = (uint32_t)__cvta_generic_to_shared(stg0);
    const uint32_t uStg1 = (uint32_t)__cvta_generic_to_shared(stg1);
    // A: matrices {rows 0-7, rows 8-15} x {k-words +0, +4}
    const int rA  = (lane & 7) + 8 * ((lane >> 3) & 1);
    const int kaA = 4 * (lane >> 4);
    const uint32_t aLane = uBuf + (uint32_t)(((m0 + rA) * LDAW + kaA) * 4);
    // B: matrices {n-group nt, k+0}, {nt, k+4}, {nt+1, k+0}, {nt+1, k+4}
    const int rB  = (lane & 7) + 8 * (lane >> 4);
    const int kaB = 4 * ((lane >> 3) & 1);
    const uint32_t bOff = (uint32_t)(((n0 + rB) * LDBW + kaB) * 4);
    const uint32_t bLane0 = uStg0 + bOff, bLane1 = uStg1 + bOff;

    uint32_t acc[4][8][2];

    // ---- layer 1: Xp(128x160) @ W1^T, 5 chunks, stages 0,1,0,1,0 ----
#pragma unroll
    for (int mt = 0; mt < 4; mt++)
#pragma unroll
        for (int nt = 0; nt < 8; nt++) { acc[mt][nt][0] = 0u; acc[mt][nt][1] = 0u; }

    const int NC1 = D_IN / KC;   // 5
    for (int c = 0; c < NC1; c++) {
        char* nextStg = ((c + 1) & 1) ? stg1 : stg0;
        if (c + 1 < NC1) prefetch_chunk(nextStg, gW1t, D_IN, c + 1);
        else             prefetch_chunk(nextStg, gW2t, HID, 0);
        CP_COMMIT();
        CP_WAIT(1);
        __syncthreads();                 // chunk c landed; prior compute done
        compute_chunk(aLane, (c & 1) ? bLane1 : bLane0, c * KC, acc);
        __syncthreads();                 // stage free before next-next prefetch
    }
    store_act(sBuf, sB1h, m0, n0, g, tig, acc);
    __syncthreads();

    // ---- layer 2: h1(128x256) @ W2^T, 8 chunks, stage parity starts at 1 ----
#pragma unroll
    for (int mt = 0; mt < 4; mt++)
#pragma unroll
        for (int nt = 0; nt < 8; nt++) { acc[mt][nt][0] = 0u; acc[mt][nt][1] = 0u; }

    const int NC2 = HID / KC;    // 8
    for (int c = 0; c < NC2; c++) {
        char* nextStg = ((c + 2) & 1) ? stg1 : stg0;   // (1+c+1)&1
        if (c + 1 < NC2) prefetch_chunk(nextStg, gW2t, HID, c + 1);
        else             prefetch_w3(nextStg);
        CP_COMMIT();
        CP_WAIT(1);
        __syncthreads();
        compute_chunk(aLane, ((1 + c) & 1) ? bLane1 : bLane0, c * KC, acc);
        __syncthreads();
    }
    store_act(sBuf, sB2h, m0, n0, g, tig, acc);
    CP_WAIT(0);                          // W3 stage landed (stage 1)
    __syncthreads();

    // ---- layer 3: h2(128x256) @ W3^T(16x256); each warp owns 16 rows ----
    {
        const uint32_t* sW3 = (const uint32_t*)stg1;
        uint32_t acc3[2][2];
        acc3[0][0] = acc3[0][1] = acc3[1][0] = acc3[1][1] = 0u;

        const int r0w = wid * 16;
#pragma unroll
        for (int k0 = 0; k0 < HID; k0 += 16) {
            int kw = k0 >> 1;
            const uint32_t* p = sBuf + (r0w + g) * LDAW + kw + tig;
            uint32_t a0 = p[0];
            uint32_t a1 = p[8 * LDAW];
            uint32_t a2 = p[4];
            uint32_t a3 = p[8 * LDAW + 4];
#pragma unroll
            for (int nt = 0; nt < 2; nt++) {
                int col = nt * 8 + g;
                const uint32_t* q = sW3 + col * LDW3 + kw + tig;
                mma16h(acc3[nt], a0, a1, a2, a3, q[0], q[4]);
            }
        }

        // ---- bias + segment reduction (RED atomics) ----
        const int rAo = r0w + g, rBo = rAo + 8;
        const int segA = sSeg[rAo], segB = sSeg[rBo];
#pragma unroll
        for (int nt = 0; nt < 2; nt++) {
            int c0 = nt * 8 + 2 * tig;
            float bv0 = sB3[c0], bv1 = sB3[c0 + 1];
            float2 lo = __half22float2(bits2h(acc3[nt][0]));
            float2 hi = __half22float2(bits2h(acc3[nt][1]));
            if (segA >= 0) {
                atomicAdd(&gSum[segA * D_OUT + c0],     lo.x + bv0);
                atomicAdd(&gSum[segA * D_OUT + c0 + 1], lo.y + bv1);
            }
            if (segB >= 0) {
                atomicAdd(&gSum[segB * D_OUT + c0],     hi.x + bv0);
                atomicAdd(&gSum[segB * D_OUT + c0 + 1], hi.y + bv1);
            }
        }
        if (tig == 0) {
            if (segA >= 0) atomicAdd(&gCnt[segA], 1.0f);
            if (segB >= 0) atomicAdd(&gCnt[segB], 1.0f);
        }
    }

    // ---- last-CTA finalize: Y = gSum / max(gCnt,1) -> d_out ----
    __threadfence();
    __syncthreads();
    if (tid == 0) {
        unsigned v = atomicAdd(&gDone, 1u);
        sLast = (v == (unsigned)(NTILES - 1)) ? 1u : 0u;
    }
    __syncthreads();
    if (sLast) {
        __threadfence();
#pragma unroll
        for (int u = 0; u < (BATCH * D_OUT) / 256; u++) {
            int i = tid + u * 256;
            float s = __ldcg(&gSum[i]);
            float c = __ldcg(&gCnt[i >> 4]);
            out[i] = s / fmaxf(c, 1.0f);
        }
    }
}

// ---------------------------------------------------------------------------
extern "C" void kernel_launch(void* const* d_in, const int* in_sizes, int n_in,
                              void* d_out, int out_size) {
    const float* X    = (const float*)d_in[0];
    const float* Z    = (const float*)d_in[1];
    const float* W1   = (const float*)d_in[2];
    const float* b1   = (const float*)d_in[3];
    const float* W2   = (const float*)d_in[4];
    const float* b2   = (const float*)d_in[5];
    const float* W3   = (const float*)d_in[6];
    const float* b3   = (const float*)d_in[7];
    const int*   c2b  = (const int*)d_in[8];    // int32 on the wire (JAX x64 off)
    const int*   sidx = (const int*)d_in[9];
    float* out = (float*)d_out;

    cudaFuncSetAttribute(fused_kernel, cudaFuncAttributeMaxDynamicSharedMemorySize,
                         SMEM_BYTES);

    prep_kernel<<<160, 256>>>(W1, W2, W3);
    fused_kernel<<<NTILES, 256, SMEM_BYTES>>>(X, Z, b1, b2, b3, c2b, sidx, out);
}

// round 17
// speedup vs baseline: 1.0888x; 1.0888x over previous
#include <cuda_runtime.h>
#include <cuda_fp16.h>
#include <cstdint>

// ---------------------------------------------------------------------------
// CompositionModel — fp16 mma.sync m16n8k16 (f16 acc) + ldmatrix, 64x64 warp
// tiles (TILE_M=128), cp.async.BULK weight staging (1 instr / 16KB chunk)
// with mbarrier pipeline, 2 CTAs/SM, last-CTA finalize.
//   Xp = [fp16(log1p X) | fp16(Z[c2b])]  (N x 160)
//   h1 = relu(Xp@W1+b1); h2 = relu(h1@W2+b2); Xc = h2@W3+b3; Y = segmean(Xc)
// R16 analysis: 13 chunks x 1024 cp.async(16B) = ~13.3K LSU-issue cyc/CTA —
// same order as MMA time. Bulk copy removes that entirely; weights are
// pre-packed chunk-contiguous in prep with the LDSM swizzle baked into the
// global layout: (n, piece j) -> n*64 + (j ^ ((n&6)>>1))*16  (conflict-free).
// One __syncthreads per chunk; consumers use mbarrier parity waits.
// ---------------------------------------------------------------------------

#define N_CELLS 500000
#define D_X     128
#define D_Z     32
#define D_IN    160
#define HID     256
#define D_OUT   16
#define BATCH   512
#define TILE_M  128
#define NTILES  ((N_CELLS + TILE_M - 1) / TILE_M)   // 3907

#define LDAW    132      // act row stride in words; 528B rows -> LDSM conflict-free
#define LDW3    132      // W3 stage row stride (words)
#define KC      32       // fp16 k per chunk (2 k-steps of 16)
#define CHUNK_BYTES 16384   // 256 n-rows x 32 k x 2B, unpadded (swizzled)
#define NCH_TOT 13          // 5 (W1) + 8 (W2)

// smem byte offsets
#define SM_BUF  0                                  // 128 x LDAW words = 67584 B
#define SM_STG0 67584                              // 16384 B
#define SM_STG1 84224                              // 16384 B (67584+16384+256 pad)
#define SM_MISC 101120
// misc: mbar[2](16B) seg[128] cb[128] b1h[128] b2h[128] b3[16]
#define SMEM_BYTES (SM_MISC + 16 + 128*4 + 128*4 + 128*4 + 128*4 + 16*4)  // 103264; x2 <= 233472

// __device__ scratch: weights chunk-packed + swizzled (see prep)
__device__ __half gW1c[5 * 8192];    // 5 chunks x (256 x 32)
__device__ __half gW2c[8 * 8192];    // 8 chunks x (256 x 32)
__device__ __half gW3t[16 * HID];    // [n][k] plain
__device__ float gSum[BATCH * D_OUT];
__device__ float gCnt[BATCH];
__device__ unsigned gDone;

// ---------------- PTX helpers ----------------
__device__ __forceinline__ void cp16(void* dst_smem, const void* src) {
    uint32_t d = (uint32_t)__cvta_generic_to_shared(dst_smem);
    asm volatile("cp.async.cg.shared.global [%0], [%1], 16;\n" :: "r"(d), "l"(src));
}
#define CP_COMMIT() asm volatile("cp.async.commit_group;\n")
#define CP_WAIT(n)  asm volatile("cp.async.wait_group %0;\n" :: "n"(n))

#define MBAR_INIT(addr, cnt) asm volatile( \
    "mbarrier.init.shared.b64 [%0], %1;" :: "r"(addr), "r"((uint32_t)(cnt)) : "memory")
#define MBAR_EXPECT_TX(addr, n) asm volatile( \
    "mbarrier.arrive.expect_tx.shared.b64 _, [%0], %1;" :: "r"(addr), "r"((uint32_t)(n)) : "memory")

__device__ __forceinline__ void mbar_wait(uint32_t addr, uint32_t parity) {
    asm volatile(
        "{\n\t.reg .pred P;\n\t"
        "WL%=:\n\t"
        "mbarrier.try_wait.parity.acquire.cta.shared::cta.b64 P, [%0], %1, 0x989680;\n\t"
        "@P bra.uni WD%=;\n\t"
        "bra.uni WL%=;\n\t"
        "WD%=:\n\t}" :: "r"(addr), "r"(parity) : "memory");
}

__device__ __forceinline__ void bulk_ld(uint32_t dst_smem, uint64_t src_global,
                                        uint32_t bytes, uint32_t mbar) {
    asm volatile(
        "cp.async.bulk.shared::cluster.global.mbarrier::complete_tx::bytes "
        "[%0], [%1], %2, [%3];"
        :: "r"(dst_smem), "l"(src_global), "r"(bytes), "r"(mbar) : "memory");
}
__device__ __forceinline__ uint64_t to_global(const void* p) {
    uint64_t g;
    asm("cvta.to.global.u64 %0, %1;" : "=l"(g) : "l"(p));
    return g;
}

// m16n8k16 fp16 inputs, FP16 accumulators (2 regs)
__device__ __forceinline__ void mma16h(uint32_t c[2],
                                       uint32_t a0, uint32_t a1, uint32_t a2, uint32_t a3,
                                       uint32_t b0, uint32_t b1) {
    asm volatile(
        "mma.sync.aligned.m16n8k16.row.col.f16.f16.f16.f16 "
        "{%0,%1}, {%2,%3,%4,%5}, {%6,%7}, {%0,%1};\n"
        : "+r"(c[0]), "+r"(c[1])
        : "r"(a0), "r"(a1), "r"(a2), "r"(a3), "r"(b0), "r"(b1));
}

__device__ __forceinline__ void ldsm_x4(uint32_t (&r)[4], uint32_t addr) {
    asm volatile("ldmatrix.sync.aligned.m8n8.x4.shared.b16 {%0,%1,%2,%3}, [%4];"
                 : "=r"(r[0]), "=r"(r[1]), "=r"(r[2]), "=r"(r[3]) : "r"(addr));
}

__device__ __forceinline__ uint32_t h2bits(__half2 h) {
    return *reinterpret_cast<uint32_t*>(&h);
}
__device__ __forceinline__ __half2 bits2h(uint32_t u) {
    return *reinterpret_cast<__half2*>(&u);
}

// prefetch W3 (16 x 256 fp16 = 8 KB) into a stage, row stride LDW3 words
__device__ __forceinline__ void prefetch_w3(char* stg) {
    int t = threadIdx.x;
#pragma unroll
    for (int u = 0; u < 2; u++) {
        int idx = t + u * 256;            // 0..511
        int n = idx >> 5, j = idx & 31;
        cp16(stg + (n * LDW3 + j * 4) * 4, gW3t + n * HID + j * 8);
    }
}

// one KC-slice of the 64x64 warp-tile GEMM via ldmatrix (2 k-steps of 16)
// bBase = stage + (n0+rB)*64 ; swizzled piece = (j ^ rBs) within the row
__device__ __forceinline__ void compute_chunk(uint32_t aLane, uint32_t bBase,
                                              uint32_t rBs, uint32_t laneJ, int kbase,
                                              uint32_t (&acc)[4][8][2]) {
#pragma unroll
    for (int kk = 0; kk < KC; kk += 16) {
        uint32_t koffA = (uint32_t)(((kbase + kk) >> 1) * 4);
        uint32_t a[4][4];
#pragma unroll
        for (int mt = 0; mt < 4; mt++)
            ldsm_x4(a[mt], aLane + mt * (16 * LDAW * 4) + koffA);
        uint32_t jl = (uint32_t)(kk >> 3) + laneJ;      // logical 16B piece
        uint32_t boff = ((jl ^ rBs) << 4);
        uint32_t b[4][4];
#pragma unroll
        for (int p = 0; p < 4; p++)
            ldsm_x4(b[p], bBase + p * (16 * 64) + boff);
#pragma unroll
        for (int p = 0; p < 4; p++)
#pragma unroll
            for (int j = 0; j < 2; j++)
#pragma unroll
                for (int mt = 0; mt < 4; mt++)
                    mma16h(acc[mt][2 * p + j],
                           a[mt][0], a[mt][1], a[mt][2], a[mt][3],
                           b[p][2 * j], b[p][2 * j + 1]);
    }
}

// f16 acc -> relu(+bias, packed) -> act buffer
__device__ __forceinline__ void store_act(uint32_t* sBuf, const uint32_t* bias2,
                                          int m0, int n0, int g, int tig,
                                          uint32_t (&acc)[4][8][2]) {
    const __half2 z2 = __float2half2_rn(0.f);
#pragma unroll
    for (int mt = 0; mt < 4; mt++) {
        int r0 = m0 + mt * 16 + g;
#pragma unroll
        for (int nt = 0; nt < 8; nt++) {
            int wc = (n0 >> 1) + nt * 4 + tig;
            __half2 bv = bits2h(bias2[wc]);
            sBuf[r0 * LDAW + wc]       = h2bits(__hmax2(__hadd2(bits2h(acc[mt][nt][0]), bv), z2));
            sBuf[(r0 + 8) * LDAW + wc] = h2bits(__hmax2(__hadd2(bits2h(acc[mt][nt][1]), bv), z2));
        }
    }
}

// ---------------------------------------------------------------------------
// prep: pack weights chunk-contiguous with LDSM swizzle baked in.
// Output fp16 index i decomposes as: c (chunk), n (0..255), p (phys 16B piece
// 0..3), e (0..7). Logical piece j = p ^ ((n&6)>>1); k = c*32 + j*8 + e.
// ---------------------------------------------------------------------------
__global__ void prep_kernel(const float* __restrict__ W1, const float* __restrict__ W2,
                            const float* __restrict__ W3) {
    int stride = gridDim.x * blockDim.x;
    int t0 = blockIdx.x * blockDim.x + threadIdx.x;
    for (int i = t0; i < 5 * 8192; i += stride) {
        int c = i >> 13, r = i & 8191;
        int n = r >> 5, q = r & 31;
        int p = q >> 3, e = q & 7;
        int j = p ^ ((n & 6) >> 1);
        int k = c * 32 + j * 8 + e;           // < 160
        gW1c[i] = __float2half_rn(W1[k * 256 + n]);
    }
    for (int i = t0; i < 8 * 8192; i += stride) {
        int c = i >> 13, r = i & 8191;
        int n = r >> 5, q = r & 31;
        int p = q >> 3, e = q & 7;
        int j = p ^ ((n & 6) >> 1);
        int k = c * 32 + j * 8 + e;           // < 256
        gW2c[i] = __float2half_rn(W2[k * 256 + n]);
    }
    for (int i = t0; i < 16 * HID; i += stride) {
        int n = i >> 8, k = i & 255;
        gW3t[i] = __float2half_rn(W3[k * 16 + n]);
    }
    for (int i = t0; i < BATCH * D_OUT; i += stride) gSum[i] = 0.f;
    for (int i = t0; i < BATCH; i += stride) gCnt[i] = 0.f;
    if (t0 == 0) gDone = 0u;
}

// ---------------------------------------------------------------------------
// 8 warps as 2(Mg of 64 rows) x 4(Ng of 64 cols); 2 CTAs resident per SM.
// Unified 13-chunk stream (W1 c0-4, W2 c5-12) with bulk+mbarrier pipeline.
// ---------------------------------------------------------------------------
__global__ __launch_bounds__(256, 2) void fused_kernel(
    const float* __restrict__ X, const float* __restrict__ Z,
    const float* __restrict__ b1, const float* __restrict__ b2,
    const float* __restrict__ b3,
    const int* __restrict__ c2b, const int* __restrict__ sidx,
    float* __restrict__ out) {
    extern __shared__ char smem[];
    uint32_t* sBuf = (uint32_t*)(smem + SM_BUF);     // 128 x LDAW words (fp16 pairs)
    char*     stg0 = smem + SM_STG0;
    char*     stg1 = smem + SM_STG1;
    int*      sSeg = (int*)(smem + SM_MISC + 16);
    int*      sCB  = sSeg + 128;
    uint32_t* sB1h = (uint32_t*)(sCB + 128);         // 128 half2 words
    uint32_t* sB2h = sB1h + 128;
    float*    sB3  = (float*)(sB2h + 128);           // 16 floats
    __shared__ unsigned sLast;

    const int tid  = threadIdx.x;
    const int lane = tid & 31;
    const int wid  = tid >> 5;
    const int g    = lane >> 2;
    const int tig  = lane & 3;
    const int base = blockIdx.x * TILE_M;

    const uint32_t uMisc = (uint32_t)__cvta_generic_to_shared(smem + SM_MISC);
    const uint32_t mb[2] = {uMisc, uMisc + 8};
    const uint32_t uStg0 = (uint32_t)__cvta_generic_to_shared(stg0);
    const uint32_t uStg1 = (uint32_t)__cvta_generic_to_shared(stg1);
    const uint64_t gW1g = to_global(gW1c);
    const uint64_t gW2g = to_global(gW2c);

    // init mbarriers + kick off chunks 0,1 (overlaps input staging)
    if (tid == 0) {
        MBAR_INIT(mb[0], 1);
        MBAR_INIT(mb[1], 1);
        MBAR_EXPECT_TX(mb[0], CHUNK_BYTES);
        bulk_ld(uStg0, gW1g, CHUNK_BYTES, mb[0]);
        MBAR_EXPECT_TX(mb[1], CHUNK_BYTES);
        bulk_ld(uStg1, gW1g + CHUNK_BYTES, CHUNK_BYTES, mb[1]);
        sLast = 0u;
    }

    // ---- indices + biases (biases packed to half2 words) ----
    if (tid < 128) {
        int c = base + tid, cb = 0, seg = -1;
        if (c < N_CELLS) { cb = c2b[c]; seg = sidx[cb]; }
        sCB[tid] = cb;
        sSeg[tid] = seg;
        sB1h[tid] = h2bits(__floats2half2_rn(b1[2 * tid], b1[2 * tid + 1]));
        sB2h[tid] = h2bits(__floats2half2_rn(b2[2 * tid], b2[2 * tid + 1]));
    }
    if (tid < 16) sB3[tid] = b3[tid];
    __syncthreads();     // mbar init + misc visible to all

    // ---- build Xp tile (fp16): words 0..63 = log1p(X), 64..79 = Z gather ----
#pragma unroll
    for (int u = 0; u < 16; u++) {               // X: 4096 float4 pieces (128 rows x 32)
        int idx = tid + u * 256;
        int row = idx >> 5, p = idx & 31;
        int cell = base + row;
        uint2 w = make_uint2(0u, 0u);
        if (cell < N_CELLS) {
            float4 x = *reinterpret_cast<const float4*>(X + (size_t)cell * D_X + p * 4);
            w.x = h2bits(__floats2half2_rn(__logf(1.f + x.x), __logf(1.f + x.y)));
            w.y = h2bits(__floats2half2_rn(__logf(1.f + x.z), __logf(1.f + x.w)));
        }
        *reinterpret_cast<uint2*>(sBuf + row * LDAW + 2 * p) = w;
    }
#pragma unroll
    for (int u = 0; u < 4; u++) {                // Z: 1024 float4 pieces (128 rows x 8)
        int idx = tid + u * 256;
        int row = idx >> 3, p = idx & 7;
        int cell = base + row;
        uint2 w = make_uint2(0u, 0u);
        if (cell < N_CELLS) {
            float4 z = *reinterpret_cast<const float4*>(Z + (size_t)sCB[row] * D_Z + p * 4);
            w.x = h2bits(__floats2half2_rn(z.x, z.y));
            w.y = h2bits(__floats2half2_rn(z.z, z.w));
        }
        *reinterpret_cast<uint2*>(sBuf + row * LDAW + 64 + 2 * p) = w;
    }
    __syncthreads();

    const int mg = wid & 1, ng = wid >> 1;
    const int m0 = mg * 64, n0 = ng * 64;

    // per-lane ldmatrix addresses
    const uint32_t uBuf = (uint32_t)__cvta_generic_to_shared(sBuf);
    // A: matrices {rows 0-7, 8-15} x {k-words +0, +4}
    const int rA  = (lane & 7) + 8 * ((lane >> 3) & 1);
    const int kaA = 4 * (lane >> 4);
    const uint32_t aLane = uBuf + (uint32_t)(((m0 + rA) * LDAW + kaA) * 4);
    // B: 16 n-rows x 16 k per x4; unpadded 64B rows, swizzled pieces
    const int rB = (lane & 7) + 8 * (lane >> 4);
    const uint32_t rBs   = (uint32_t)((rB & 6) >> 1);
    const uint32_t laneJ = (uint32_t)((lane >> 3) & 1);
    const uint32_t bB[2] = {uStg0 + (uint32_t)((n0 + rB) * 64),
                            uStg1 + (uint32_t)((n0 + rB) * 64)};

    uint32_t acc[4][8][2];
#pragma unroll
    for (int mt = 0; mt < 4; mt++)
#pragma unroll
        for (int nt = 0; nt < 8; nt++) { acc[mt][nt][0] = 0u; acc[mt][nt][1] = 0u; }

    // ---- unified chunk stream: c0-4 = layer1 (Xp@W1), c5-12 = layer2 (h1@W2) ----
    int ph0 = 0, ph1 = 0;
    for (int c = 0; c < NCH_TOT; c++) {
        if (c == 5) {
            // layer boundary: all reads of Xp done (trailing sync of c=4)
            store_act(sBuf, sB1h, m0, n0, g, tig, acc);
#pragma unroll
            for (int mt = 0; mt < 4; mt++)
#pragma unroll
                for (int nt = 0; nt < 8; nt++) { acc[mt][nt][0] = 0u; acc[mt][nt][1] = 0u; }
            __syncthreads();            // h1 visible before layer-2 LDSM
        }
        if (c == 12) {                  // stage1's last bulk use was c=11
            prefetch_w3(stg1);
            CP_COMMIT();
        }
        int s = c & 1;
        if (s) { mbar_wait(mb[1], (uint32_t)ph1); ph1 ^= 1; }
        else   { mbar_wait(mb[0], (uint32_t)ph0); ph0 ^= 1; }
        int kbase = (c < 5) ? c * KC : (c - 5) * KC;
        compute_chunk(aLane, bB[s], rBs, laneJ, kbase, acc);
        __syncthreads();                // all warps done reading stage s
        if (tid == 0 && c + 2 < NCH_TOT) {
            int cn = c + 2;
            uint64_t src = (cn < 5) ? (gW1g + (uint64_t)cn * CHUNK_BYTES)
                                    : (gW2g + (uint64_t)(cn - 5) * CHUNK_BYTES);
            MBAR_EXPECT_TX(mb[s], CHUNK_BYTES);
            bulk_ld(s ? uStg1 : uStg0, src, CHUNK_BYTES, mb[s]);
        }
    }
    store_act(sBuf, sB2h, m0, n0, g, tig, acc);
    CP_WAIT(0);                         // this thread's W3 copies done
    __syncthreads();                    // everyone's W3 + h2 visible

    // ---- layer 3: h2(128x256) @ W3^T(16x256); each warp owns 16 rows ----
    {
        const uint32_t* sW3 = (const uint32_t*)stg1;
        uint32_t acc3[2][2];
        acc3[0][0] = acc3[0][1] = acc3[1][0] = acc3[1][1] = 0u;

        const int r0w = wid * 16;
#pragma unroll
        for (int k0 = 0; k0 < HID; k0 += 16) {
            int kw = k0 >> 1;
            const uint32_t* p = sBuf + (r0w + g) * LDAW + kw + tig;
            uint32_t a0 = p[0];
            uint32_t a1 = p[8 * LDAW];
            uint32_t a2 = p[4];
            uint32_t a3 = p[8 * LDAW + 4];
#pragma unroll
            for (int nt = 0; nt < 2; nt++) {
                int col = nt * 8 + g;
                const uint32_t* q = sW3 + col * LDW3 + kw + tig;
                mma16h(acc3[nt], a0, a1, a2, a3, q[0], q[4]);
            }
        }

        // ---- bias + segment reduction (RED atomics) ----
        const int rAo = r0w + g, rBo = rAo + 8;
        const int segA = sSeg[rAo], segB = sSeg[rBo];
#pragma unroll
        for (int nt = 0; nt < 2; nt++) {
            int c0 = nt * 8 + 2 * tig;
            float bv0 = sB3[c0], bv1 = sB3[c0 + 1];
            float2 lo = __half22float2(bits2h(acc3[nt][0]));
            float2 hi = __half22float2(bits2h(acc3[nt][1]));
            if (segA >= 0) {
                atomicAdd(&gSum[segA * D_OUT + c0],     lo.x + bv0);
                atomicAdd(&gSum[segA * D_OUT + c0 + 1], lo.y + bv1);
            }
            if (segB >= 0) {
                atomicAdd(&gSum[segB * D_OUT + c0],     hi.x + bv0);
                atomicAdd(&gSum[segB * D_OUT + c0 + 1], hi.y + bv1);
            }
        }
        if (tig == 0) {
            if (segA >= 0) atomicAdd(&gCnt[segA], 1.0f);
            if (segB >= 0) atomicAdd(&gCnt[segB], 1.0f);
        }
    }

    // ---- last-CTA finalize: Y = gSum / max(gCnt,1) -> d_out ----
    __threadfence();
    __syncthreads();
    if (tid == 0) {
        unsigned v = atomicAdd(&gDone, 1u);
        sLast = (v == (unsigned)(NTILES - 1)) ? 1u : 0u;
    }
    __syncthreads();
    if (sLast) {
        __threadfence();
#pragma unroll
        for (int u = 0; u < (BATCH * D_OUT) / 256; u++) {
            int i = tid + u * 256;
            float s = __ldcg(&gSum[i]);
            float c = __ldcg(&gCnt[i >> 4]);
            out[i] = s / fmaxf(c, 1.0f);
        }
    }
}

// ---------------------------------------------------------------------------
extern "C" void kernel_launch(void* const* d_in, const int* in_sizes, int n_in,
                              void* d_out, int out_size) {
    const float* X    = (const float*)d_in[0];
    const float* Z    = (const float*)d_in[1];
    const float* W1   = (const float*)d_in[2];
    const float* b1   = (const float*)d_in[3];
    const float* W2   = (const float*)d_in[4];
    const float* b2   = (const float*)d_in[5];
    const float* W3   = (const float*)d_in[6];
    const float* b3   = (const float*)d_in[7];
    const int*   c2b  = (const int*)d_in[8];    // int32 on the wire (JAX x64 off)
    const int*   sidx = (const int*)d_in[9];
    float* out = (float*)d_out;

    cudaFuncSetAttribute(fused_kernel, cudaFuncAttributeMaxDynamicSharedMemorySize,
                         SMEM_BYTES);

    prep_kernel<<<160, 256>>>(W1, W2, W3);
    fused_kernel<<<NTILES, 256, SMEM_BYTES>>>(X, Z, b1, b2, b3, c2b, sidx, out);
}